// round 13
// baseline (speedup 1.0000x reference)
#include <cuda_runtime.h>
#include <stdint.h>

#define BB 32
#define TT 64
#define NN 4096   // TT*TT
#define KK 80
#define DD 512

#define NT 512            // threads per block
#define KPT (NN / NT)     // 8 keys per thread
#define GPB 4             // blocks per batch (redundant select, split gather)
#define RPG (KK / GPB)    // 20 rows gathered per block
#define GRID (BB * GPB)   // 128 blocks -> single wave on 148 SMs

#define NBIN0 4096        // 12-bit first radix digit
#define BPT   (NBIN0 / NT)  // 8 bins/thread in pass-0 scan
#define CAND  256         // candidate capacity

// Fully independent blocks: each block redundantly computes the exact top-80
// for its batch (deterministic -> all 4 blocks of a batch agree), then
// gathers its own 20 rows. No inter-block communication of any kind.
__global__ __launch_bounds__(NT, 2)
void proposal_kernel(const float* __restrict__ logit,
                     const float* __restrict__ map2d,
                     const float* __restrict__ offset_gt,
                     const float* __restrict__ tmap,
                     float* __restrict__ out) {
    __shared__ unsigned int       hist[NBIN0];     // 16 KB
    __shared__ unsigned int       s_warp[16];
    __shared__ unsigned long long cand[CAND];      // 2 KB
    __shared__ int                s_idx[KK];
    __shared__ unsigned int       s_cnt;
    __shared__ int                s_bin;
    __shared__ unsigned int       s_high, s_C;

    const int bid   = blockIdx.x;
    const int t     = threadIdx.x;
    const int lane  = t & 31;
    const int warp  = t >> 5;
    const int b     = bid >> 2;     // batch
    const int chunk = bid & 3;      // which 20-row slice this block gathers

    const size_t O1 = (size_t)BB * KK * DD;       // pred_s_e
    const size_t O2 = O1 + (size_t)BB * KK * 2;   // offset_gt_list
    const size_t O3 = O2 + (size_t)BB * KK * 2;   // pred_score

    // ---- encode 8 monotone 32-bit float keys per thread -------------------
    // Full 48-bit sort key (built on the fly): K = (u << 16) | ((4095-i) << 4)
    // All K distinct; equal floats tie-break toward smaller idx (matches
    // jax.lax.top_k stable order). v == 0 -> -inf mask.
    unsigned int key[KPT];
    const float* base = logit + (size_t)b * NN;
#pragma unroll
    for (int e = 0; e < KPT; e++) {
        float v = base[e * NT + t];
        unsigned int u;
        if (v == 0.0f) {
            u = 0u;
        } else {
            u = __float_as_uint(v);
            u = (u & 0x80000000u) ? ~u : (u | 0x80000000u);
        }
        key[e] = u;
    }

    // ---- radix select: 12-bit pass, then 8/8/8/8/4-bit refinements --------
    // Early exit as soon as the TOTAL candidate set (all keys >= bin floor,
    // including keys above earlier-pass boundary bins) fits in CAND.
    // Final pass resolves all 48 bits -> exact for any input.
    unsigned long long pref   = 0;
    unsigned long long thresh = 0;
    unsigned int remK = KK;
    bool done = false;

    const int shifts[6] = {36, 28, 20, 12, 4, 0};
    const int widths[6] = {12,  8,  8,  8, 8, 4};

    for (int pass = 0; pass < 6 && !done; pass++) {
        const int sh = shifts[pass];
        const int w  = widths[pass];
        const unsigned int dmask = (1u << w) - 1u;

        if (pass == 0) {
#pragma unroll
            for (int r = 0; r < BPT; r++) hist[t + r * NT] = 0;
        } else {
            if (t < 256) hist[t] = 0;
        }
        __syncthreads();

        // warp-aggregated histogram (leader atomicAdd is fire-and-forget)
#pragma unroll
        for (int e = 0; e < KPT; e++) {
            const int i = e * NT + t;
            const unsigned long long K =
                ((unsigned long long)key[e] << 16)
                | (unsigned int)((NN - 1 - i) << 4);
            const bool m = (pass == 0) || ((K >> (sh + w)) == pref);
            const unsigned int mv = __ballot_sync(0xffffffffu, m);
            if (m) {
                const unsigned int d = (unsigned int)(K >> sh) & dmask;
                const unsigned int peers = __match_any_sync(mv, d);
                if (lane == (__ffs(peers) - 1))
                    atomicAdd(&hist[d], (unsigned int)__popc(peers));
            }
        }
        __syncthreads();

        if (pass == 0) {
            // 4096-bin suffix scan; thread t owns bins [t*8, t*8+8)
            unsigned int h[BPT];
            unsigned int tot = 0;
#pragma unroll
            for (int j = 0; j < BPT; j++) {
                h[j] = hist[t * BPT + j];
                tot += h[j];
            }
            unsigned int s = tot;
#pragma unroll
            for (int off = 1; off < 32; off <<= 1) {
                unsigned int o = __shfl_down_sync(0xffffffffu, s, off);
                if (lane + off < 32) s += o;
            }
            if (lane == 0) s_warp[warp] = s;
            __syncthreads();
            unsigned int hi = 0;
#pragma unroll
            for (int w2 = 0; w2 < 16; w2++)
                if (w2 > warp) hi += s_warp[w2];
            const unsigned int above = (s - tot) + hi;  // strictly above own bins
            unsigned int suf = above;
#pragma unroll
            for (int j = BPT - 1; j >= 0; j--) {
                const unsigned int sufj = suf + h[j];   // suffix(bin j) inclusive
                if (sufj >= remK && suf < remK) {
                    s_bin = t * BPT + j; s_high = suf; s_C = sufj;
                }
                suf = sufj;
            }
        } else {
            // 256-bin suffix scan (threads 0..255)
            unsigned int s = (t < 256) ? hist[t] : 0u;
#pragma unroll
            for (int off = 1; off < 32; off <<= 1) {
                unsigned int o = __shfl_down_sync(0xffffffffu, s, off);
                if (lane + off < 32) s += o;
            }
            if (t < 256 && lane == 0) s_warp[warp] = s;
            __syncthreads();
            if (t < 256) {
                unsigned int hi = 0;
#pragma unroll
                for (int w2 = 0; w2 < 8; w2++)
                    if (w2 > warp) hi += s_warp[w2];
                const unsigned int S   = s + hi;        // suffix(t)
                const unsigned int Sn  = S - hist[t];   // suffix(t+1)
                if (S >= remK && Sn < remK) {
                    s_bin = t; s_high = Sn; s_C = S;
                }
            }
        }
        __syncthreads();

        // total candidates >= thresh = keys above earlier boundary bins
        // (KK - remK) + this pass's inclusive suffix s_C
        const unsigned int ctot = (KK - remK) + s_C;

        pref   = (pref << w) | (unsigned int)s_bin;
        thresh = pref << sh;
        remK  -= s_high;
        if (ctot <= (unsigned int)CAND) done = true;
        if (!done) __syncthreads();   // protect hist/s_bin reuse next pass
    }

    // ---- collect candidates (all keys >= thresh; count <= CAND) -----------
    if (t == 0) s_cnt = 0;
    if (t < CAND) cand[t] = 0ULL;
    __syncthreads();
#pragma unroll
    for (int e = 0; e < KPT; e++) {
        const int i = e * NT + t;
        const unsigned long long K =
            ((unsigned long long)key[e] << 16)
            | (unsigned int)((NN - 1 - i) << 4);
        if (K >= thresh) {
            const unsigned int pos = atomicAdd(&s_cnt, 1u);
            if (pos < CAND) cand[pos] = K;
        }
    }
    __syncthreads();

    // ---- exact order via rank-counting (distinct keys; pads=0 sink) -------
    if (t < CAND) {
        const unsigned long long k = cand[t];
        int rank = 0;
#pragma unroll 8
        for (int j = 0; j < CAND; j++)
            rank += (cand[j] > k);          // broadcast smem reads

        if (k != 0ULL && rank < KK) {
            const int idx = (NN - 1) - (int)((k >> 4) & 0xFFFu);
            s_idx[rank] = idx;

            if (chunk == 0) {               // one block per batch writes scalars
                const int row = idx >> 6;
                const int col = idx & 63;
                const int blk = b * KK + rank;
                out[O1 + blk * 2 + 0] = (float)row;
                out[O1 + blk * 2 + 1] = (float)(col + 1);
                float2 og = ((const float2*)offset_gt)[(size_t)b * NN + idx];
                ((float2*)(out + O2))[blk] = og;
                out[O3 + blk] = tmap[(size_t)b * NN + idx];
            }
        }
    }
    __syncthreads();

    // ---- gather this block's 20 rows (5 independent float4s per thread) ---
    const int sub = t >> 7;                 // 0..3
    const int col = t & 127;                // float4 column 0..127
    const int r0  = chunk * RPG + sub * 5;  // local ranks r0..r0+4

    int rowi[5];
#pragma unroll
    for (int j = 0; j < 5; j++)
        rowi[j] = s_idx[r0 + j];

    float4 v[5];
#pragma unroll
    for (int j = 0; j < 5; j++) {
        const float4* src =
            (const float4*)(map2d + ((size_t)b * NN + rowi[j]) * DD);
        v[j] = src[col];
    }
#pragma unroll
    for (int j = 0; j < 5; j++) {
        float4* dst = (float4*)(out + (size_t)(b * KK + r0 + j) * DD);
        dst[col] = v[j];
    }
}

extern "C" void kernel_launch(void* const* d_in, const int* in_sizes, int n_in,
                              void* d_out, int out_size) {
    const float* selection_logit = (const float*)d_in[0];
    const float* map2d           = (const float*)d_in[1];
    const float* offset_gt       = (const float*)d_in[2];
    const float* tmap            = (const float*)d_in[3];
    float* out = (float*)d_out;

    proposal_kernel<<<GRID, NT>>>(selection_logit, map2d, offset_gt, tmap, out);
}